// round 5
// baseline (speedup 1.0000x reference)
#include <cuda_runtime.h>

#define BB 8
#define SS 1024
#define EE 768
#define HH 12
#define DD 64
#define MTOT (BB*SS)      // 8192
#define N3 (3*EE)         // 2304

// Scratch (allocation-free rule: __device__ globals)
__device__ float g_q[BB*HH*SS*DD];   // [B,H,S,D]
__device__ float g_k[BB*HH*SS*DD];
__device__ float g_v[BB*HH*SS*DD];
__device__ float g_o[BB*SS*EE];      // attention output [B,S,E]

// ---------------------------------------------------------------------------
// Kernel 1: qkv = x @ w_qkv + b, scattered into q/k/v as [B,H,S,D]
// 128x128 tile, BK=8, 256 threads, 8x8 per thread. All dims exact multiples.
// ---------------------------------------------------------------------------
__global__ __launch_bounds__(256) void qkv_gemm_kernel(
    const float* __restrict__ X,     // [8192, 768]
    const float* __restrict__ W,     // [768, 2304]
    const float* __restrict__ bias)  // [2304]
{
    __shared__ float As[8][128];   // transposed: As[k][m]
    __shared__ float Bs[8][128];   // Bs[k][n]

    const int bx = blockIdx.x;     // 0..17 (N tiles)
    const int by = blockIdx.y;     // 0..63 (M tiles)
    const int tid = (int)threadIdx.x;
    const int tr = tid >> 4;       // 0..15
    const int tc = tid & 15;       // 0..15

    const int n0 = bx * 128;
    const int m0 = by * 128;

    // A-load mapping: one float4 per thread per k-step
    const int arow = tid >> 1;          // 0..127
    const int acol = (tid & 1) * 4;     // 0 or 4
    // B-load mapping
    const int brow = tid >> 5;          // 0..7
    const int bcol = (tid & 31) * 4;    // 0..124

    const float* Aptr = X + (long)(m0 + arow) * EE + acol;
    const float* Bptr = W + (long)brow * N3 + n0 + bcol;

    float acc[8][8];
    #pragma unroll
    for (int i = 0; i < 8; i++)
        #pragma unroll
        for (int j = 0; j < 8; j++) acc[i][j] = 0.f;

    for (int k0 = 0; k0 < EE; k0 += 8) {
        float4 av = *(const float4*)(Aptr + k0);
        As[acol + 0][arow] = av.x;
        As[acol + 1][arow] = av.y;
        As[acol + 2][arow] = av.z;
        As[acol + 3][arow] = av.w;
        *(float4*)&Bs[brow][bcol] = *(const float4*)(Bptr + (long)k0 * N3);
        __syncthreads();

        #pragma unroll
        for (int kk = 0; kk < 8; kk++) {
            float4 a0 = *(const float4*)&As[kk][tr * 8];
            float4 a1 = *(const float4*)&As[kk][tr * 8 + 4];
            float4 b0 = *(const float4*)&Bs[kk][tc * 8];
            float4 b1 = *(const float4*)&Bs[kk][tc * 8 + 4];
            float a[8] = {a0.x, a0.y, a0.z, a0.w, a1.x, a1.y, a1.z, a1.w};
            float b[8] = {b0.x, b0.y, b0.z, b0.w, b1.x, b1.y, b1.z, b1.w};
            #pragma unroll
            for (int i = 0; i < 8; i++)
                #pragma unroll
                for (int j = 0; j < 8; j++)
                    acc[i][j] += a[i] * b[j];
        }
        __syncthreads();
    }

    // Epilogue: +bias, scatter. Whole n-tile is inside one of q/k/v (768 = 6*128).
    const int which = n0 / EE;                      // 0=q 1=k 2=v
    float* dst = (which == 0) ? g_q : ((which == 1) ? g_k : g_v);
    const int cbase = n0 - which * EE + tc * 8;     // col within [0,768)
    const int h  = cbase >> 6;
    const int d0 = cbase & 63;                      // thread's 8 cols never cross a head

    float br[8];
    #pragma unroll
    for (int j = 0; j < 8; j++) br[j] = bias[n0 + tc * 8 + j];

    #pragma unroll
    for (int i = 0; i < 8; i++) {
        int m  = m0 + tr * 8 + i;
        int b_ = m >> 10;
        int s_ = m & 1023;
        float* p = dst + (((long)(b_ * HH + h) * SS + s_) * DD + d0);
        float4 v0 = make_float4(acc[i][0] + br[0], acc[i][1] + br[1],
                                acc[i][2] + br[2], acc[i][3] + br[3]);
        float4 v1 = make_float4(acc[i][4] + br[4], acc[i][5] + br[5],
                                acc[i][6] + br[6], acc[i][7] + br[7]);
        *(float4*)p       = v0;
        *(float4*)(p + 4) = v1;
    }
}

// ---------------------------------------------------------------------------
// Kernel 2: flash attention (fp32, online softmax).
// Block = (query-tile of 64, h, b). 256 threads, 4x4 micro-tiles.
// Smem: Qs[d][i], KPs (K^T [d][j], reused as P [j][i]), Vs[j][d] = 48KB exact.
// ---------------------------------------------------------------------------
__global__ __launch_bounds__(256) void attn_kernel()
{
    __shared__ float Qs[64][64];
    __shared__ float KPs[64][64];
    __shared__ float Vs[64][64];

    const int qt = blockIdx.x;     // 0..15
    const int h  = blockIdx.y;     // 0..11
    const int b  = blockIdx.z;     // 0..7
    const int tid = (int)threadIdx.x;
    const int tr = tid >> 4;       // 0..15 -> rows tr*4..+3
    const int tc = tid & 15;       // 0..15 -> cols tc*4..+3

    const long bh = (long)(b * HH + h) * SS;
    const float* Q = g_q + bh * DD;
    const float* K = g_k + bh * DD;
    const float* V = g_v + bh * DD;
    const int i0 = qt * 64;

    // Load Q transposed into Qs[d][i]
    {
        int i = tid >> 2;
        int dbase = (tid & 3) * 16;
        const float* src = Q + (long)(i0 + i) * DD + dbase;
        #pragma unroll
        for (int q = 0; q < 4; q++) {
            float4 v = *(const float4*)(src + q * 4);
            int d = dbase + q * 4;
            Qs[d + 0][i] = v.x;
            Qs[d + 1][i] = v.y;
            Qs[d + 2][i] = v.z;
            Qs[d + 3][i] = v.w;
        }
    }

    float m_r[4], l_r[4], acc_o[4][4];
    #pragma unroll
    for (int ii = 0; ii < 4; ii++) {
        m_r[ii] = -1e30f;
        l_r[ii] = 0.f;
        #pragma unroll
        for (int jj = 0; jj < 4; jj++) acc_o[ii][jj] = 0.f;
    }

    const float scale = 0.125f;   // 1/sqrt(64)

    for (int j0 = 0; j0 < SS; j0 += 64) {
        // K tile transposed -> KPs[d][j]
        {
            int j = tid >> 2;
            int dbase = (tid & 3) * 16;
            const float* src = K + (long)(j0 + j) * DD + dbase;
            #pragma unroll
            for (int q = 0; q < 4; q++) {
                float4 v = *(const float4*)(src + q * 4);
                int d = dbase + q * 4;
                KPs[d + 0][j] = v.x;
                KPs[d + 1][j] = v.y;
                KPs[d + 2][j] = v.z;
                KPs[d + 3][j] = v.w;
            }
        }
        // V tile direct -> Vs[j][d]
        {
            const float* src = V + (long)j0 * DD;
            #pragma unroll
            for (int r = 0; r < 4; r++) {
                int idx = tid + 256 * r;      // float4 index 0..1023
                int j = idx >> 4;
                int d = (idx & 15) * 4;
                *(float4*)&Vs[j][d] = *(const float4*)(src + j * DD + d);
            }
        }
        __syncthreads();

        // S = Q K^T (unscaled)
        float s_acc[4][4];
        #pragma unroll
        for (int ii = 0; ii < 4; ii++)
            #pragma unroll
            for (int jj = 0; jj < 4; jj++) s_acc[ii][jj] = 0.f;

        #pragma unroll 8
        for (int kk = 0; kk < 64; kk++) {
            float4 a = *(const float4*)&Qs[kk][tr * 4];     // broadcast in 16-lane group
            float4 bq = *(const float4*)&KPs[kk][tc * 4];   // conflict-free
            float av[4] = {a.x, a.y, a.z, a.w};
            float bv[4] = {bq.x, bq.y, bq.z, bq.w};
            #pragma unroll
            for (int ii = 0; ii < 4; ii++)
                #pragma unroll
                for (int jj = 0; jj < 4; jj++)
                    s_acc[ii][jj] += av[ii] * bv[jj];
        }
        __syncthreads();   // all done reading KPs; safe to overwrite with P

        // Online softmax (row groups = 16 consecutive lanes; xor<=8 stays in group)
        float p[4][4];
        #pragma unroll
        for (int ii = 0; ii < 4; ii++) {
            float mx = fmaxf(fmaxf(s_acc[ii][0], s_acc[ii][1]),
                             fmaxf(s_acc[ii][2], s_acc[ii][3]));
            #pragma unroll
            for (int off = 8; off >= 1; off >>= 1)
                mx = fmaxf(mx, __shfl_xor_sync(0xffffffffu, mx, off));
            mx *= scale;
            float m_new = fmaxf(m_r[ii], mx);
            float corr = __expf(m_r[ii] - m_new);
            float sum = 0.f;
            #pragma unroll
            for (int jj = 0; jj < 4; jj++) {
                float pv = __expf(s_acc[ii][jj] * scale - m_new);
                p[ii][jj] = pv;
                sum += pv;
            }
            #pragma unroll
            for (int off = 8; off >= 1; off >>= 1)
                sum += __shfl_xor_sync(0xffffffffu, sum, off);
            l_r[ii] = l_r[ii] * corr + sum;
            m_r[ii] = m_new;
            #pragma unroll
            for (int jj = 0; jj < 4; jj++) acc_o[ii][jj] *= corr;
        }

        // P -> smem transposed [j][i]
        #pragma unroll
        for (int jj = 0; jj < 4; jj++)
            #pragma unroll
            for (int ii = 0; ii < 4; ii++)
                KPs[tc * 4 + jj][tr * 4 + ii] = p[ii][jj];
        __syncthreads();

        // acc_o += P @ V
        #pragma unroll 8
        for (int j = 0; j < 64; j++) {
            float4 a = *(const float4*)&KPs[j][tr * 4];     // broadcast
            float4 bq = *(const float4*)&Vs[j][tc * 4];     // conflict-free
            float av[4] = {a.x, a.y, a.z, a.w};
            float bv[4] = {bq.x, bq.y, bq.z, bq.w};
            #pragma unroll
            for (int ii = 0; ii < 4; ii++)
                #pragma unroll
                for (int jj = 0; jj < 4; jj++)
                    acc_o[ii][jj] += av[ii] * bv[jj];
        }
        __syncthreads();   // before next tile overwrites KPs/Vs
    }

    // O write: row i0+tr*4+ii, cols h*64 + tc*4..+3
    #pragma unroll
    for (int ii = 0; ii < 4; ii++) {
        float inv = 1.f / l_r[ii];
        int i = i0 + tr * 4 + ii;
        float* dst = g_o + (long)(b * SS + i) * EE + h * 64 + tc * 4;
        *(float4*)dst = make_float4(acc_o[ii][0] * inv, acc_o[ii][1] * inv,
                                    acc_o[ii][2] * inv, acc_o[ii][3] * inv);
    }
}

// ---------------------------------------------------------------------------
// Kernel 3: y = LN(x + attn_out) * gamma + beta   (one block per row)
// ---------------------------------------------------------------------------
__global__ __launch_bounds__(256) void ln_kernel(
    const float* __restrict__ X,
    const float* __restrict__ gamma,
    const float* __restrict__ beta,
    float* __restrict__ out)
{
    __shared__ float ssum[8], ssq[8];
    const int row = blockIdx.x;
    const int tid = (int)threadIdx.x;
    const float* xr = X + (long)row * EE;
    const float* orow = g_o + (long)row * EE;

    float y[3];
    float sum = 0.f, sq = 0.f;
    #pragma unroll
    for (int r = 0; r < 3; r++) {
        int e = tid + 256 * r;
        float v = xr[e] + orow[e];
        y[r] = v;
        sum += v;
        sq += v * v;
    }
    #pragma unroll
    for (int off = 16; off >= 1; off >>= 1) {
        sum += __shfl_xor_sync(0xffffffffu, sum, off);
        sq  += __shfl_xor_sync(0xffffffffu, sq, off);
    }
    int warp = tid >> 5, lane = tid & 31;
    if (lane == 0) { ssum[warp] = sum; ssq[warp] = sq; }
    __syncthreads();
    if (warp == 0) {
        float s = (lane < 8) ? ssum[lane] : 0.f;
        float q = (lane < 8) ? ssq[lane] : 0.f;
        #pragma unroll
        for (int off = 4; off >= 1; off >>= 1) {
            s += __shfl_xor_sync(0xffffffffu, s, off);
            q += __shfl_xor_sync(0xffffffffu, q, off);
        }
        if (lane == 0) { ssum[0] = s; ssq[0] = q; }
    }
    __syncthreads();
    const float inv_e = 1.f / (float)EE;
    float mean = ssum[0] * inv_e;
    float var  = ssq[0] * inv_e - mean * mean;
    float rstd = rsqrtf(var + 1e-5f);
    #pragma unroll
    for (int r = 0; r < 3; r++) {
        int e = tid + 256 * r;
        out[(long)row * EE + e] = (y[r] - mean) * rstd * gamma[e] + beta[e];
    }
}

// ---------------------------------------------------------------------------
extern "C" void kernel_launch(void* const* d_in, const int* in_sizes, int n_in,
                              void* d_out, int out_size)
{
    const float* x     = (const float*)d_in[0];
    const float* w_qkv = (const float*)d_in[1];
    const float* b_qkv = (const float*)d_in[2];
    const float* gamma = (const float*)d_in[3];
    const float* beta  = (const float*)d_in[4];
    float* out = (float*)d_out;

    dim3 g1(N3 / 128, MTOT / 128);          // 18 x 64
    qkv_gemm_kernel<<<g1, 256>>>(x, w_qkv, b_qkv);

    dim3 g2(SS / 64, HH, BB);               // 16 x 12 x 8
    attn_kernel<<<g2, 256>>>();

    ln_kernel<<<MTOT, 256>>>(x, gamma, beta, out);
}